// round 6
// baseline (speedup 1.0000x reference)
#include <cuda_runtime.h>
#include <math.h>
#include <stdint.h>

// ----------------------------------------------------------------------------
// Problem constants
// ----------------------------------------------------------------------------
#define TT   2048
#define BB   32
#define HH   512
#define NB   64              // CTAs per direction
#define CPB  8               // hidden columns per CTA
#define STR  516             // SMEM row stride in floats

#define NTHREADS 384         // 256 consumer + 128 producer
#define RD    6              // x-preact ring depth (steps ahead)
#define RSLOT 776            // floats per ring slot (32*24 = 768 + pad)

// ----------------------------------------------------------------------------
// Device scratch
// ----------------------------------------------------------------------------
__device__ float    g_h[2][2][BB * HH];    // [dir][parity][b*H + j]
__device__ unsigned g_grp[2][8];           // two-level barrier: group counters
__device__ unsigned g_root[2];             // root counters
__device__ unsigned g_gen[2];              // generations (monotonic)

struct Args {
    const float* x;
    const float* Wxi[2][3];   // [dir][{Wri,Wci,Wni}]  (I x H row-major)
    const float* Whh[2][3];   // [dir][{Wrh,Wch,Wnh}]  (H x H row-major)
    const float* br[2];
    const float* bi[2];
    const float* bni[2];
    const float* bnh[2];
    float*       out;
};

__device__ __forceinline__ void ffma2(unsigned long long& d,
                                      unsigned long long a, unsigned long long b)
{
    asm("fma.rn.f32x2 %0, %1, %2, %0;" : "+l"(d) : "l"(a), "l"(b));
}
__device__ __forceinline__ float u64lo(unsigned long long v) {
    return __uint_as_float((unsigned)(v & 0xffffffffull));
}
__device__ __forceinline__ float u64hi(unsigned long long v) {
    return __uint_as_float((unsigned)(v >> 32));
}

#define BARC() asm volatile("bar.sync 1, 256;" ::: "memory")   // consumers
#define BARP() asm volatile("bar.sync 2, 128;" ::: "memory")   // producers

// Two-level arrive (called by consumer tid 0 only)
__device__ __forceinline__ void dir_arrive(int d, int grp)
{
    __threadfence();
    unsigned a = atomicAdd(&g_grp[d][grp], 1u);
    if (((a + 1u) & 7u) == 0u) {
        __threadfence();
        unsigned r = atomicAdd(&g_root[d], 1u);
        if (((r + 1u) & 7u) == 0u)
            atomicAdd(&g_gen[d], 1u);
    }
}
__device__ __forceinline__ void dir_wait(int d, unsigned base, unsigned target)
{
    while ((*(volatile unsigned*)&g_gen[d]) - base < target) { }
    __threadfence();
}

// ----------------------------------------------------------------------------
// Fused persistent kernel, warp-specialized:
//   warps 0-7  (256 thr): recurrence consumers (serial critical path only)
//   warps 8-11 (128 thr): x-projection producers (run ahead into SMEM ring)
// ----------------------------------------------------------------------------
__global__ void __launch_bounds__(NTHREADS, 1) gru_fused(Args p)
{
    extern __shared__ float smem[];
    float* Wh   = smem;                    // [24][STR]  rows: jl*3 + gate
    float* Wx   = Wh + 24 * STR;           // [24][STR]
    float* hbuf = Wx + 24 * STR;           // [32][STR]
    float* ring = hbuf + 32 * STR;         // [RD][RSLOT]  (b*24 + jl*3 + g)
    volatile int* s_ready = (volatile int*)(ring + RD * RSLOT);
    volatile int* s_cons  = s_ready + 1;

    const int tid = threadIdx.x;
    const int dir = blockIdx.x / NB;
    const int blk = blockIdx.x % NB;
    const int j0  = blk * CPB;

    if (tid == 0) { *s_ready = 0; *s_cons = 0; }

    // Load + transpose both weight slices with all 384 threads.
    for (int idx = tid; idx < 3 * HH * CPB; idx += NTHREADS) {
        int g  = idx >> 12;
        int k  = (idx >> 3) & (HH - 1);
        int jl = idx & 7;
        Wh[(jl * 3 + g) * STR + k] = p.Whh[dir][g][(size_t)k * HH + j0 + jl];
        Wx[(jl * 3 + g) * STR + k] = p.Wxi[dir][g][(size_t)k * HH + j0 + jl];
    }
    __syncthreads();

    float* out = p.out;

    if (tid < 256) {
        // =================== CONSUMER WARPS ===================
        const int s    = tid & 15;                    // k-split lane
        const int tt   = tid >> 4;
        const int jp   = (tt >> 1) & 3;               // j-pair
        const int bsel = (tt & 1) | ((tt >> 3) << 1);
        const int b0   = bsel * 8;
        const int myb  = b0 + (s & 7);
        const int jl_o = jp * 2 + (s >> 3);
        const int jcol = j0 + jl_o;
        const float c_bnh = p.bnh[dir][jcol];

        unsigned base = 0;
        if (tid == 0) base = *(volatile unsigned*)&g_gen[dir];

        // h0 = 0
        g_h[dir][0][myb * HH + jcol] = 0.0f;
        BARC();
        if (tid == 0) dir_arrive(dir, blk >> 3);

        const float* WhB = &Wh[jp * 6 * STR];
        const float* hbase = &hbuf[b0 * STR];

        for (int st = 0; st < TT; ++st) {
            const int t   = dir ? (TT - 1 - st) : st;
            const int par = st & 1;

            if (tid == 0) dir_wait(dir, base, (unsigned)(st + 1));
            BARC();

            // stage h(t) -> hbuf (L1-bypassing; producers are other SMs)
            {
                const float4* hsrc = (const float4*)g_h[dir][par];
                #pragma unroll
                for (int r = 0; r < 16; ++r) {
                    int idx = tid + r * 256;
                    float4 v = __ldcv(hsrc + idx);
                    int bb = idx >> 7;
                    int kk = (idx & 127) << 2;
                    *(float4*)&hbuf[bb * STR + kk] = v;
                }
            }
            BARC();

            // h-GEMM: acc[bb][jj*3+ch], ch: 0=r, 1=c, 2=nh
            unsigned long long acc[8][6];
            #pragma unroll
            for (int bb = 0; bb < 8; ++bb)
                #pragma unroll
                for (int q = 0; q < 6; ++q) acc[bb][q] = 0ull;

            #pragma unroll 4
            for (int i = 0; i < 8; ++i) {
                const int kk = (s << 2) + (i << 6);
                ulonglong2 w0 = *(const ulonglong2*)&WhB[0 * STR + kk];
                ulonglong2 w1 = *(const ulonglong2*)&WhB[1 * STR + kk];
                ulonglong2 w2 = *(const ulonglong2*)&WhB[2 * STR + kk];
                ulonglong2 w3 = *(const ulonglong2*)&WhB[3 * STR + kk];
                ulonglong2 w4 = *(const ulonglong2*)&WhB[4 * STR + kk];
                ulonglong2 w5 = *(const ulonglong2*)&WhB[5 * STR + kk];
                #pragma unroll
                for (int bb = 0; bb < 8; ++bb) {
                    ulonglong2 hv = *(const ulonglong2*)&hbase[bb * STR + kk];
                    ffma2(acc[bb][0], hv.x, w0.x);  ffma2(acc[bb][0], hv.y, w0.y);
                    ffma2(acc[bb][1], hv.x, w1.x);  ffma2(acc[bb][1], hv.y, w1.y);
                    ffma2(acc[bb][2], hv.x, w2.x);  ffma2(acc[bb][2], hv.y, w2.y);
                    ffma2(acc[bb][3], hv.x, w3.x);  ffma2(acc[bb][3], hv.y, w3.y);
                    ffma2(acc[bb][4], hv.x, w4.x);  ffma2(acc[bb][4], hv.y, w4.y);
                    ffma2(acc[bb][5], hv.x, w5.x);  ffma2(acc[bb][5], hv.y, w5.y);
                }
            }

            float a64[8][6];
            #pragma unroll
            for (int bb = 0; bb < 8; ++bb)
                #pragma unroll
                for (int q = 0; q < 6; ++q)
                    a64[bb][q] = u64lo(acc[bb][q]) + u64hi(acc[bb][q]);

            // targeted exchange reduction over 16 k-lanes (3 channels)
            const bool hi8 = (s & 8) != 0;
            float r32[8][3];
            #pragma unroll
            for (int bb = 0; bb < 8; ++bb)
                #pragma unroll
                for (int ch = 0; ch < 3; ++ch) {
                    float mine = hi8 ? a64[bb][3 + ch] : a64[bb][ch];
                    float oth  = hi8 ? a64[bb][ch]     : a64[bb][3 + ch];
                    r32[bb][ch] = mine + __shfl_xor_sync(0xffffffffu, oth, 8);
                }
            const bool hi4 = (s & 4) != 0;
            float r16[4][3];
            #pragma unroll
            for (int bl = 0; bl < 4; ++bl)
                #pragma unroll
                for (int ch = 0; ch < 3; ++ch) {
                    float mine = hi4 ? r32[bl + 4][ch] : r32[bl][ch];
                    float oth  = hi4 ? r32[bl][ch]     : r32[bl + 4][ch];
                    r16[bl][ch] = mine + __shfl_xor_sync(0xffffffffu, oth, 4);
                }
            const bool hi2 = (s & 2) != 0;
            float r8[2][3];
            #pragma unroll
            for (int bl = 0; bl < 2; ++bl)
                #pragma unroll
                for (int ch = 0; ch < 3; ++ch) {
                    float mine = hi2 ? r16[bl + 2][ch] : r16[bl][ch];
                    float oth  = hi2 ? r16[bl][ch]     : r16[bl + 2][ch];
                    r8[bl][ch] = mine + __shfl_xor_sync(0xffffffffu, oth, 2);
                }
            const bool hi1 = (s & 1) != 0;
            float ar, ac, anh;
            {
                float m0 = hi1 ? r8[1][0] : r8[0][0];
                float o0 = hi1 ? r8[0][0] : r8[1][0];
                ar = m0 + __shfl_xor_sync(0xffffffffu, o0, 1);
                float m1 = hi1 ? r8[1][1] : r8[0][1];
                float o1 = hi1 ? r8[0][1] : r8[1][1];
                ac = m1 + __shfl_xor_sync(0xffffffffu, o1, 1);
                float m2 = hi1 ? r8[1][2] : r8[0][2];
                float o2 = hi1 ? r8[0][2] : r8[1][2];
                anh = m2 + __shfl_xor_sync(0xffffffffu, o2, 1);
            }

            // wait for producer ring slot (normally far ahead)
            while (*s_ready < st + 1) { }
            __threadfence_block();
            const float* rs = &ring[(st % RD) * RSLOT + myb * 24 + jl_o * 3];
            const float gr = rs[0];
            const float gc = rs[1];
            const float gn = rs[2];

            const float rg = 1.0f / (1.0f + __expf(-(gr + ar)));
            const float cg = 1.0f / (1.0f + __expf(-(gc + ac)));
            const float ng = tanhf(gn + rg * (anh + c_bnh));
            const float hold = hbuf[myb * STR + jcol];
            const float hnew = ng + cg * (hold - ng);

            g_h[dir][par ^ 1][myb * HH + jcol] = hnew;
            out[((size_t)t * BB + myb) * (2 * HH) + dir * HH + jcol] = hnew;

            BARC();
            if (tid == 0) {
                dir_arrive(dir, blk >> 3);
                *s_cons = st + 1;          // free ring slot
            }
        }
    } else {
        // =================== PRODUCER WARPS ===================
        const int ptid = tid - 256;
        const int lane = ptid & 31;
        const int s8   = lane & 7;          // k-split lane (3 bits)
        const int rsel = (lane >> 3) & 3;   // row group (6 rows each)
        const int bsel = ptid >> 5;         // producer warp id = batch group
        const int b0   = bsel * 8;

        // lane ownership after reduction: jl = rsel*2 + (lane&1)
        const int jl_p = rsel * 2 + (lane & 1);
        float bias_q[3];
        bias_q[0] = p.br [dir][j0 + jl_p];
        bias_q[1] = p.bi [dir][j0 + jl_p];
        bias_q[2] = p.bni[dir][j0 + jl_p];

        const float* WxB = &Wx[(rsel * 6) * STR];

        for (int st = 0; st < TT; ++st) {
            const int t = dir ? (TT - 1 - st) : st;

            // wait for ring space
            while (st >= *s_cons + RD) { }

            const float* xrow = p.x + ((size_t)t * BB + b0) * HH;

            unsigned long long acc[8][6];
            #pragma unroll
            for (int bb = 0; bb < 8; ++bb)
                #pragma unroll
                for (int q = 0; q < 6; ++q) acc[bb][q] = 0ull;

            #pragma unroll 2
            for (int i = 0; i < 16; ++i) {
                const int kk = (s8 << 2) + (i << 5);
                ulonglong2 w0 = *(const ulonglong2*)&WxB[0 * STR + kk];
                ulonglong2 w1 = *(const ulonglong2*)&WxB[1 * STR + kk];
                ulonglong2 w2 = *(const ulonglong2*)&WxB[2 * STR + kk];
                ulonglong2 w3 = *(const ulonglong2*)&WxB[3 * STR + kk];
                ulonglong2 w4 = *(const ulonglong2*)&WxB[4 * STR + kk];
                ulonglong2 w5 = *(const ulonglong2*)&WxB[5 * STR + kk];
                #pragma unroll
                for (int bb = 0; bb < 8; ++bb) {
                    ulonglong2 xv = __ldg((const ulonglong2*)(xrow + (size_t)bb * HH + kk));
                    ffma2(acc[bb][0], xv.x, w0.x);  ffma2(acc[bb][0], xv.y, w0.y);
                    ffma2(acc[bb][1], xv.x, w1.x);  ffma2(acc[bb][1], xv.y, w1.y);
                    ffma2(acc[bb][2], xv.x, w2.x);  ffma2(acc[bb][2], xv.y, w2.y);
                    ffma2(acc[bb][3], xv.x, w3.x);  ffma2(acc[bb][3], xv.y, w3.y);
                    ffma2(acc[bb][4], xv.x, w4.x);  ffma2(acc[bb][4], xv.y, w4.y);
                    ffma2(acc[bb][5], xv.x, w5.x);  ffma2(acc[bb][5], xv.y, w5.y);
                }
            }

            float a64[8][6];
            #pragma unroll
            for (int bb = 0; bb < 8; ++bb)
                #pragma unroll
                for (int q = 0; q < 6; ++q)
                    a64[bb][q] = u64lo(acc[bb][q]) + u64hi(acc[bb][q]);

            // targeted reduce over 8 k-lanes (lane bits 0-2)
            const bool p1 = (lane & 1) != 0;          // row halves
            float rA[8][3];
            #pragma unroll
            for (int bb = 0; bb < 8; ++bb)
                #pragma unroll
                for (int q = 0; q < 3; ++q) {
                    float mine = p1 ? a64[bb][3 + q] : a64[bb][q];
                    float oth  = p1 ? a64[bb][q]     : a64[bb][3 + q];
                    rA[bb][q] = mine + __shfl_xor_sync(0xffffffffu, oth, 1);
                }
            const bool p2 = (lane & 2) != 0;          // bb halves
            float rB[4][3];
            #pragma unroll
            for (int bl = 0; bl < 4; ++bl)
                #pragma unroll
                for (int q = 0; q < 3; ++q) {
                    float mine = p2 ? rA[bl + 4][q] : rA[bl][q];
                    float oth  = p2 ? rA[bl][q]     : rA[bl + 4][q];
                    rB[bl][q] = mine + __shfl_xor_sync(0xffffffffu, oth, 2);
                }
            const bool p4 = (lane & 4) != 0;          // bb quarters
            float rC[2][3];
            #pragma unroll
            for (int bl = 0; bl < 2; ++bl)
                #pragma unroll
                for (int q = 0; q < 3; ++q) {
                    float mine = p4 ? rB[bl + 2][q] : rB[bl][q];
                    float oth  = p4 ? rB[bl][q]     : rB[bl + 2][q];
                    rC[bl][q] = mine + __shfl_xor_sync(0xffffffffu, oth, 4);
                }

            // owned: bb = 4*p2 + 2*p4 + bl ; store preacts + bias to ring
            float* slot = &ring[(st % RD) * RSLOT];
            #pragma unroll
            for (int bl = 0; bl < 2; ++bl) {
                int bb = (p2 ? 4 : 0) + (p4 ? 2 : 0) + bl;
                int bidx = (b0 + bb) * 24 + jl_p * 3;
                slot[bidx + 0] = rC[bl][0] + bias_q[0];
                slot[bidx + 1] = rC[bl][1] + bias_q[1];
                slot[bidx + 2] = rC[bl][2] + bias_q[2];
            }

            BARP();                         // drains STS of all producer warps
            if (ptid == 0) *s_ready = st + 1;
        }
    }
}

// ----------------------------------------------------------------------------
// Launch. Input order: x, Wri_f,Wci_f,Wni_f,Wrh_f,Wch_f,Wnh_f,br_f,bi_f,bni_f,
// bnh_f, Wri_b,Wci_b,Wni_b,Wrh_b,Wch_b,Wnh_b,br_b,bi_b,bni_b,bnh_b
// ----------------------------------------------------------------------------
extern "C" void kernel_launch(void* const* d_in, const int* in_sizes, int n_in,
                              void* d_out, int out_size)
{
    (void)in_sizes; (void)n_in; (void)out_size;

    Args a;
    a.x = (const float*)d_in[0];
    a.Wxi[0][0] = (const float*)d_in[1];
    a.Wxi[0][1] = (const float*)d_in[2];
    a.Wxi[0][2] = (const float*)d_in[3];
    a.Whh[0][0] = (const float*)d_in[4];
    a.Whh[0][1] = (const float*)d_in[5];
    a.Whh[0][2] = (const float*)d_in[6];
    a.br [0] = (const float*)d_in[7];
    a.bi [0] = (const float*)d_in[8];
    a.bni[0] = (const float*)d_in[9];
    a.bnh[0] = (const float*)d_in[10];
    a.Wxi[1][0] = (const float*)d_in[11];
    a.Wxi[1][1] = (const float*)d_in[12];
    a.Wxi[1][2] = (const float*)d_in[13];
    a.Whh[1][0] = (const float*)d_in[14];
    a.Whh[1][1] = (const float*)d_in[15];
    a.Whh[1][2] = (const float*)d_in[16];
    a.br [1] = (const float*)d_in[17];
    a.bi [1] = (const float*)d_in[18];
    a.bni[1] = (const float*)d_in[19];
    a.bnh[1] = (const float*)d_in[20];
    a.out = (float*)d_out;

    const int smem = (48 * STR + 32 * STR + RD * RSLOT) * (int)sizeof(float) + 32;
    cudaFuncSetAttribute(gru_fused, cudaFuncAttributeMaxDynamicSharedMemorySize, smem);
    gru_fused<<<2 * NB, NTHREADS, smem>>>(a);
}

// round 7
// speedup vs baseline: 1.5424x; 1.5424x over previous
#include <cuda_runtime.h>
#include <math.h>
#include <stdint.h>

// ----------------------------------------------------------------------------
// Problem constants
// ----------------------------------------------------------------------------
#define TT   2048
#define BB   32
#define HH   512
#define NB   64              // CTAs per direction
#define CPB  8               // hidden columns per CTA
#define STR  516             // SMEM row stride in floats

// ----------------------------------------------------------------------------
// Device scratch
// ----------------------------------------------------------------------------
__device__ float    g_h[2][2][BB * HH];    // [dir][parity][b*H + j]
__device__ unsigned g_grp[2][8];           // tree barrier: 8 group counters/dir
__device__ unsigned g_root[2];             // root counters
__device__ unsigned g_gen[2];              // generations (monotonic)

struct Args {
    const float* x;
    const float* Wxi[2][3];   // [dir][{Wri,Wci,Wni}]  (I x H, row-major)
    const float* Whh[2][3];   // [dir][{Wrh,Wch,Wnh}]  (H x H, row-major)
    const float* br[2];
    const float* bi[2];
    const float* bni[2];
    const float* bnh[2];
    float*       out;
};

// Packed fp32x2 FMA
__device__ __forceinline__ void ffma2(unsigned long long& d,
                                      unsigned long long a, unsigned long long b)
{
    asm("fma.rn.f32x2 %0, %1, %2, %0;" : "+l"(d) : "l"(a), "l"(b));
}
__device__ __forceinline__ float u64lo(unsigned long long v) {
    return __uint_as_float((unsigned)(v & 0xffffffffull));
}
__device__ __forceinline__ float u64hi(unsigned long long v) {
    return __uint_as_float((unsigned)(v >> 32));
}

// Two-level (8x8) arrive tree; free-running counters, monotonic gen.
__device__ __forceinline__ void bar_arrive(int d, int grp)
{
    if (threadIdx.x == 0) {
        __threadfence();
        unsigned a = atomicAdd(&g_grp[d][grp], 1u);
        if (((a + 1u) & 7u) == 0u) {
            unsigned r = atomicAdd(&g_root[d], 1u);
            if (((r + 1u) & 7u) == 0u)
                atomicAdd(&g_gen[d], 1u);
        }
    }
}
__device__ __forceinline__ void bar_wait(int d, unsigned base, unsigned target)
{
    if (threadIdx.x == 0) {
        while ((*(volatile unsigned*)&g_gen[d]) - base < target) { }
        __threadfence();
    }
    __syncthreads();
}

// Fast, overflow-safe activations
__device__ __forceinline__ float fast_sigmoid(float z) {
    return __fdividef(1.0f, 1.0f + __expf(-z));
}
__device__ __forceinline__ float fast_tanh(float z) {
    float a = fabsf(z);
    float e = __expf(-2.0f * a);               // e in (0,1], no overflow
    float t = __fdividef(1.0f - e, 1.0f + e);
    return copysignf(t, z);
}

// ----------------------------------------------------------------------------
// Fused persistent kernel (R4 skeleton + overlap + tree barrier):
// per step: stage x -> x-GEMM[0..3] -> wait -> {h-load chunk | x-GEMM[4..7]}
//           interleaved -> h-GEMM -> reduce -> activations -> arrive
// ----------------------------------------------------------------------------
__global__ void __launch_bounds__(256, 1) gru_fused(Args p)
{
    extern __shared__ float smem[];
    float* Wx   = smem;                  // [24][STR]  rows: jl*3 + gate
    float* Wh   = Wx + 24 * STR;         // [24][STR]
    float* xbuf = Wh + 24 * STR;         // [32][STR]  staged x(t)
    float* hbuf = xbuf + 32 * STR;       // [32][STR]  staged h(t)

    const int tid = threadIdx.x;
    const int dir = blockIdx.x / NB;
    const int blk = blockIdx.x % NB;
    const int grp = blk >> 3;
    const int j0  = blk * CPB;

    const int s    = tid & 15;                    // k-split lane
    const int tt   = tid >> 4;
    const int jp   = (tt >> 1) & 3;               // j-pair
    const int bsel = (tt & 1) | ((tt >> 3) << 1);
    const int b0   = bsel * 8;

    __shared__ unsigned s_base;
    if (tid == 0) s_base = *(volatile unsigned*)&g_gen[dir];

    // Load + transpose weight slices: W*[jl*3+g][k] = W_g[k][j0+jl]
    for (int idx = tid; idx < 3 * HH * CPB; idx += 256) {
        int g  = idx >> 12;
        int k  = (idx >> 3) & (HH - 1);
        int jl = idx & 7;
        Wx[(jl * 3 + g) * STR + k] = p.Wxi[dir][g][(size_t)k * HH + j0 + jl];
        Wh[(jl * 3 + g) * STR + k] = p.Whh[dir][g][(size_t)k * HH + j0 + jl];
    }

    // each thread owns exactly one (b, j) output
    const int myb  = b0 + (s & 7);
    const int jcol = j0 + jp * 2 + (s >> 3);
    const float c_br  = p.br [dir][jcol];
    const float c_bi  = p.bi [dir][jcol];
    const float c_bni = p.bni[dir][jcol];
    const float c_bnh = p.bnh[dir][jcol];

    // h0 = 0 (parity 0)
    g_h[dir][0][myb * HH + jcol] = 0.0f;
    __syncthreads();
    const unsigned base = s_base;
    bar_arrive(dir, grp);                 // signals h0 ready

    const float* WxB = &Wx[jp * 6 * STR];
    const float* WhB = &Wh[jp * 6 * STR];
    float* out = p.out;

    // x-GEMM macro body for one k-block i (channels r=0, c=1, n_x=2)
#define XG_ITER(i)                                                              \
    {                                                                           \
        const int kk = (s << 2) + ((i) << 6);                                   \
        ulonglong2 w0 = *(const ulonglong2*)&WxB[0 * STR + kk];                 \
        ulonglong2 w1 = *(const ulonglong2*)&WxB[1 * STR + kk];                 \
        ulonglong2 w2 = *(const ulonglong2*)&WxB[2 * STR + kk];                 \
        ulonglong2 w3 = *(const ulonglong2*)&WxB[3 * STR + kk];                 \
        ulonglong2 w4 = *(const ulonglong2*)&WxB[4 * STR + kk];                 \
        ulonglong2 w5 = *(const ulonglong2*)&WxB[5 * STR + kk];                 \
        _Pragma("unroll")                                                       \
        for (int bb = 0; bb < 8; ++bb) {                                        \
            ulonglong2 xv = *(const ulonglong2*)&xbuf[(b0 + bb) * STR + kk];    \
            ffma2(acc[bb][0], xv.x, w0.x);  ffma2(acc[bb][0], xv.y, w0.y);      \
            ffma2(acc[bb][1], xv.x, w1.x);  ffma2(acc[bb][1], xv.y, w1.y);      \
            ffma2(acc[bb][2], xv.x, w2.x);  ffma2(acc[bb][2], xv.y, w2.y);      \
            ffma2(acc[bb][4], xv.x, w3.x);  ffma2(acc[bb][4], xv.y, w3.y);      \
            ffma2(acc[bb][5], xv.x, w4.x);  ffma2(acc[bb][5], xv.y, w4.y);      \
            ffma2(acc[bb][6], xv.x, w5.x);  ffma2(acc[bb][6], xv.y, w5.y);      \
        }                                                                       \
    }

    for (int st = 0; st < TT; ++st) {
        const int t   = dir ? (TT - 1 - st) : st;
        const int par = st & 1;

        // ---- stage x(t) -> xbuf ----
        {
            const float4* xs = (const float4*)(p.x + (size_t)t * BB * HH);
            #pragma unroll
            for (int r = 0; r < 16; ++r) {
                int idx = tid + r * 256;
                float4 v = __ldg(xs + idx);
                int bb = idx >> 7;
                int kk = (idx & 127) << 2;
                *(float4*)&xbuf[bb * STR + kk] = v;
            }
        }
        __syncthreads();

        // accumulators: [bb][jj*4 + ch], ch: 0=r, 1=c, 2=n_x, 3=n_h
        unsigned long long acc[8][8];
        #pragma unroll
        for (int bb = 0; bb < 8; ++bb)
            #pragma unroll
            for (int q = 0; q < 8; ++q) acc[bb][q] = 0ull;

        // ---- x-GEMM first half: hides barrier release chain ----
        XG_ITER(0)  XG_ITER(1)  XG_ITER(2)  XG_ITER(3)

        // ---- wait for h(t) ----
        bar_wait(dir, base, (unsigned)(st + 1));

        // ---- x-GEMM tail interleaved with h staging (hide L2 latency) ----
        {
            const float4* hsrc = (const float4*)g_h[dir][par];
            #pragma unroll
            for (int c = 0; c < 4; ++c) {
                float4 v0 = __ldcv(hsrc + (tid + (4 * c + 0) * 256));
                float4 v1 = __ldcv(hsrc + (tid + (4 * c + 1) * 256));
                float4 v2 = __ldcv(hsrc + (tid + (4 * c + 2) * 256));
                float4 v3 = __ldcv(hsrc + (tid + (4 * c + 3) * 256));
                switch (c) {
                    case 0: XG_ITER(4) break;
                    case 1: XG_ITER(5) break;
                    case 2: XG_ITER(6) break;
                    case 3: XG_ITER(7) break;
                }
                #pragma unroll
                for (int u = 0; u < 4; ++u) {
                    int idx = tid + (4 * c + u) * 256;
                    int bb = idx >> 7;
                    int kk = (idx & 127) << 2;
                    float4 v = (u == 0) ? v0 : (u == 1) ? v1 : (u == 2) ? v2 : v3;
                    *(float4*)&hbuf[bb * STR + kk] = v;
                }
            }
        }
        __syncthreads();

        // ---- h-GEMM (channels r, c, n_h) ----
        #pragma unroll
        for (int i = 0; i < 8; ++i) {
            const int kk = (s << 2) + (i << 6);
            ulonglong2 w0 = *(const ulonglong2*)&WhB[0 * STR + kk];
            ulonglong2 w1 = *(const ulonglong2*)&WhB[1 * STR + kk];
            ulonglong2 w2 = *(const ulonglong2*)&WhB[2 * STR + kk];
            ulonglong2 w3 = *(const ulonglong2*)&WhB[3 * STR + kk];
            ulonglong2 w4 = *(const ulonglong2*)&WhB[4 * STR + kk];
            ulonglong2 w5 = *(const ulonglong2*)&WhB[5 * STR + kk];
            #pragma unroll
            for (int bb = 0; bb < 8; ++bb) {
                ulonglong2 hv = *(const ulonglong2*)&hbuf[(b0 + bb) * STR + kk];
                ffma2(acc[bb][0], hv.x, w0.x);  ffma2(acc[bb][0], hv.y, w0.y);
                ffma2(acc[bb][1], hv.x, w1.x);  ffma2(acc[bb][1], hv.y, w1.y);
                ffma2(acc[bb][3], hv.x, w2.x);  ffma2(acc[bb][3], hv.y, w2.y);
                ffma2(acc[bb][4], hv.x, w3.x);  ffma2(acc[bb][4], hv.y, w3.y);
                ffma2(acc[bb][5], hv.x, w4.x);  ffma2(acc[bb][5], hv.y, w4.y);
                ffma2(acc[bb][7], hv.x, w5.x);  ffma2(acc[bb][7], hv.y, w5.y);
            }
        }

        // ---- collapse f32x2 pairs -> f32 ----
        float a64[8][8];
        #pragma unroll
        for (int bb = 0; bb < 8; ++bb)
            #pragma unroll
            for (int q = 0; q < 8; ++q)
                a64[bb][q] = u64lo(acc[bb][q]) + u64hi(acc[bb][q]);

        // ---- targeted exchange reduction over the 16 k-split lanes ----
        const bool hi8 = (s & 8) != 0;
        float r32[8][4];
        #pragma unroll
        for (int bb = 0; bb < 8; ++bb)
            #pragma unroll
            for (int ch = 0; ch < 4; ++ch) {
                float mine = hi8 ? a64[bb][4 + ch] : a64[bb][ch];
                float oth  = hi8 ? a64[bb][ch]     : a64[bb][4 + ch];
                r32[bb][ch] = mine + __shfl_xor_sync(0xffffffffu, oth, 8);
            }
        const bool hi4 = (s & 4) != 0;
        float r16[4][4];
        #pragma unroll
        for (int bl = 0; bl < 4; ++bl)
            #pragma unroll
            for (int ch = 0; ch < 4; ++ch) {
                float mine = hi4 ? r32[bl + 4][ch] : r32[bl][ch];
                float oth  = hi4 ? r32[bl][ch]     : r32[bl + 4][ch];
                r16[bl][ch] = mine + __shfl_xor_sync(0xffffffffu, oth, 4);
            }
        const bool hi2 = (s & 2) != 0;
        float r8[2][4];
        #pragma unroll
        for (int bl = 0; bl < 2; ++bl)
            #pragma unroll
            for (int ch = 0; ch < 4; ++ch) {
                float mine = hi2 ? r16[bl + 2][ch] : r16[bl][ch];
                float oth  = hi2 ? r16[bl][ch]     : r16[bl + 2][ch];
                r8[bl][ch] = mine + __shfl_xor_sync(0xffffffffu, oth, 2);
            }
        const bool hi1 = (s & 1) != 0;
        float r4v[4];
        #pragma unroll
        for (int ch = 0; ch < 4; ++ch) {
            float mine = hi1 ? r8[1][ch] : r8[0][ch];
            float oth  = hi1 ? r8[0][ch] : r8[1][ch];
            r4v[ch] = mine + __shfl_xor_sync(0xffffffffu, oth, 1);
        }

        // ---- activations + state update ----
        const float rg = fast_sigmoid(r4v[0] + c_br);
        const float cg = fast_sigmoid(r4v[1] + c_bi);
        const float ng = fast_tanh(r4v[2] + c_bni + rg * (r4v[3] + c_bnh));
        const float hold = hbuf[myb * STR + jcol];
        const float hnew = ng + cg * (hold - ng);

        g_h[dir][par ^ 1][myb * HH + jcol] = hnew;
        out[((size_t)t * BB + myb) * (2 * HH) + dir * HH + jcol] = hnew;

        __syncthreads();
        bar_arrive(dir, grp);
    }
#undef XG_ITER
}

// ----------------------------------------------------------------------------
// Launch. Input order: x, Wri_f,Wci_f,Wni_f,Wrh_f,Wch_f,Wnh_f,br_f,bi_f,bni_f,
// bnh_f, Wri_b,Wci_b,Wni_b,Wrh_b,Wch_b,Wnh_b,br_b,bi_b,bni_b,bnh_b
// ----------------------------------------------------------------------------
extern "C" void kernel_launch(void* const* d_in, const int* in_sizes, int n_in,
                              void* d_out, int out_size)
{
    (void)in_sizes; (void)n_in; (void)out_size;

    Args a;
    a.x = (const float*)d_in[0];
    a.Wxi[0][0] = (const float*)d_in[1];
    a.Wxi[0][1] = (const float*)d_in[2];
    a.Wxi[0][2] = (const float*)d_in[3];
    a.Whh[0][0] = (const float*)d_in[4];
    a.Whh[0][1] = (const float*)d_in[5];
    a.Whh[0][2] = (const float*)d_in[6];
    a.br [0] = (const float*)d_in[7];
    a.bi [0] = (const float*)d_in[8];
    a.bni[0] = (const float*)d_in[9];
    a.bnh[0] = (const float*)d_in[10];
    a.Wxi[1][0] = (const float*)d_in[11];
    a.Wxi[1][1] = (const float*)d_in[12];
    a.Wxi[1][2] = (const float*)d_in[13];
    a.Whh[1][0] = (const float*)d_in[14];
    a.Whh[1][1] = (const float*)d_in[15];
    a.Whh[1][2] = (const float*)d_in[16];
    a.br [1] = (const float*)d_in[17];
    a.bi [1] = (const float*)d_in[18];
    a.bni[1] = (const float*)d_in[19];
    a.bnh[1] = (const float*)d_in[20];
    a.out = (float*)d_out;

    const int smem = (48 * STR + 64 * STR) * (int)sizeof(float);   // ~231 KB
    cudaFuncSetAttribute(gru_fused, cudaFuncAttributeMaxDynamicSharedMemorySize, smem);
    gru_fused<<<2 * NB, 256, smem>>>(a);
}

// round 8
// speedup vs baseline: 1.6467x; 1.0676x over previous
#include <cuda_runtime.h>
#include <math.h>
#include <stdint.h>

// ----------------------------------------------------------------------------
// Problem constants
// ----------------------------------------------------------------------------
#define TT   2048
#define BB   32
#define HH   512
#define NB   64              // CTAs per direction
#define CPB  8               // hidden columns per CTA
#define STR  516             // SMEM row stride in floats
#define NG   4               // independent groups per CTA (8 batch rows each)
#define GB   8               // batch rows per group

// ----------------------------------------------------------------------------
// Device scratch: 8 independent barrier networks (2 dirs x 4 groups)
// ----------------------------------------------------------------------------
__device__ float    g_h[2][2][BB * HH];        // [dir][parity][b*H + j]
__device__ unsigned g_grp[2][NG][8];           // tree leaves (8 groups of 8 CTAs)
__device__ unsigned g_root[2][NG];
__device__ unsigned g_gen[2][NG];              // monotonic generations

struct Args {
    const float* x;
    const float* Wxi[2][3];   // [dir][{Wri,Wci,Wni}]  (I x H, row-major)
    const float* Whh[2][3];   // [dir][{Wrh,Wch,Wnh}]  (H x H, row-major)
    const float* br[2];
    const float* bi[2];
    const float* bni[2];
    const float* bnh[2];
    float*       out;
};

// Packed fp32x2 FMA
__device__ __forceinline__ void ffma2(unsigned long long& d,
                                      unsigned long long a, unsigned long long b)
{
    asm("fma.rn.f32x2 %0, %1, %2, %0;" : "+l"(d) : "l"(a), "l"(b));
}
__device__ __forceinline__ float u64lo(unsigned long long v) {
    return __uint_as_float((unsigned)(v & 0xffffffffull));
}
__device__ __forceinline__ float u64hi(unsigned long long v) {
    return __uint_as_float((unsigned)(v >> 32));
}

// Scoped atomics: no full membar (avoids CCTL.IVALL L1 flush per step)
__device__ __forceinline__ unsigned atom_add_acqrel(unsigned* p, unsigned v)
{
    unsigned old;
    asm volatile("atom.acq_rel.gpu.add.u32 %0, [%1], %2;"
                 : "=r"(old) : "l"(p), "r"(v) : "memory");
    return old;
}
__device__ __forceinline__ unsigned ld_acquire(const unsigned* p)
{
    unsigned v;
    asm volatile("ld.acquire.gpu.u32 %0, [%1];" : "=r"(v) : "l"(p) : "memory");
    return v;
}

// Per-network arrive tree (called by group leader only). acq_rel atomics give
// cumulative release ordering: group's h stores (ordered by bar.sync) are
// visible before gen increments.
__device__ __forceinline__ void net_arrive(int d, int g, int grpIdx)
{
    unsigned a = atom_add_acqrel(&g_grp[d][g][grpIdx], 1u);
    if (((a + 1u) & 7u) == 0u) {
        unsigned r = atom_add_acqrel(&g_root[d][g], 1u);
        if (((r + 1u) & 7u) == 0u)
            atom_add_acqrel(&g_gen[d][g], 1u);
    }
}

// Group-scoped named barrier (64 threads, ids 1..4)
#define GBAR(g) asm volatile("bar.sync %0, 64;" :: "r"((g) + 1) : "memory")

// Fast, overflow-safe activations
__device__ __forceinline__ float fast_sigmoid(float z) {
    return __fdividef(1.0f, 1.0f + __expf(-z));
}
__device__ __forceinline__ float fast_tanh(float z) {
    float a = fabsf(z);
    float e = __expf(-2.0f * a);
    float t = __fdividef(1.0f - e, 1.0f + e);
    return copysignf(t, z);
}

// ----------------------------------------------------------------------------
// Fused persistent kernel, 4 independent batch-groups per CTA.
// Group step: stage x -> bar -> x-GEMM -> wait(own net) -> stage h -> bar ->
//             h-GEMM -> reduce -> activations -> store -> bar -> arrive
// ----------------------------------------------------------------------------
__global__ void __launch_bounds__(256, 1) gru_fused(Args p)
{
    extern __shared__ float smem[];
    float* Wx   = smem;                  // [24][STR]  rows: jl*3 + gate
    float* Wh   = Wx + 24 * STR;         // [24][STR]
    float* xbuf = Wh + 24 * STR;         // [32][STR]  (partitioned per group)
    float* hbuf = xbuf + 32 * STR;       // [32][STR]

    const int tid = threadIdx.x;
    const int dir = blockIdx.x / NB;
    const int blk = blockIdx.x % NB;
    const int grpIdx = blk >> 3;
    const int j0  = blk * CPB;

    const int g    = tid >> 6;           // group 0..3
    const int tidg = tid & 63;
    const int s    = tidg & 15;          // k-split lane
    const int jp   = tidg >> 4;          // j-pair 0..3
    const int b0   = g * GB;             // group's batch base
    const bool leader = (tidg == 0);

    // Load + transpose weight slices with all 256 threads
    for (int idx = tid; idx < 3 * HH * CPB; idx += 256) {
        int gg = idx >> 12;
        int k  = (idx >> 3) & (HH - 1);
        int jl = idx & 7;
        Wx[(jl * 3 + gg) * STR + k] = p.Wxi[dir][gg][(size_t)k * HH + j0 + jl];
        Wh[(jl * 3 + gg) * STR + k] = p.Whh[dir][gg][(size_t)k * HH + j0 + jl];
    }
    __syncthreads();

    // each thread owns one (b, j) output
    const int myb  = b0 + (s & 7);
    const int jcol = j0 + jp * 2 + (s >> 3);
    const float c_br  = p.br [dir][jcol];
    const float c_bi  = p.bi [dir][jcol];
    const float c_bni = p.bni[dir][jcol];
    const float c_bnh = p.bnh[dir][jcol];

    unsigned base = 0;
    if (leader) base = ld_acquire(&g_gen[dir][g]);

    // h0 = 0
    g_h[dir][0][myb * HH + jcol] = 0.0f;
    GBAR(g);
    if (leader) net_arrive(dir, g, grpIdx);

    const float* WxB = &Wx[jp * 6 * STR];
    const float* WhB = &Wh[jp * 6 * STR];
    float* out = p.out;

#define GEMM_ITER(WB, BUF, c0, c1, c2)                                          \
    {                                                                           \
        const int kk = (s << 2) + (i << 6);                                     \
        ulonglong2 w0 = *(const ulonglong2*)&WB[0 * STR + kk];                  \
        ulonglong2 w1 = *(const ulonglong2*)&WB[1 * STR + kk];                  \
        ulonglong2 w2 = *(const ulonglong2*)&WB[2 * STR + kk];                  \
        ulonglong2 w3 = *(const ulonglong2*)&WB[3 * STR + kk];                  \
        ulonglong2 w4 = *(const ulonglong2*)&WB[4 * STR + kk];                  \
        ulonglong2 w5 = *(const ulonglong2*)&WB[5 * STR + kk];                  \
        _Pragma("unroll")                                                       \
        for (int bb = 0; bb < 8; ++bb) {                                        \
            ulonglong2 v = *(const ulonglong2*)&BUF[(b0 + bb) * STR + kk];      \
            ffma2(acc[bb][c0],     v.x, w0.x);  ffma2(acc[bb][c0],     v.y, w0.y); \
            ffma2(acc[bb][c1],     v.x, w1.x);  ffma2(acc[bb][c1],     v.y, w1.y); \
            ffma2(acc[bb][c2],     v.x, w2.x);  ffma2(acc[bb][c2],     v.y, w2.y); \
            ffma2(acc[bb][4 + c0], v.x, w3.x);  ffma2(acc[bb][4 + c0], v.y, w3.y); \
            ffma2(acc[bb][4 + c1], v.x, w4.x);  ffma2(acc[bb][4 + c1], v.y, w4.y); \
            ffma2(acc[bb][4 + c2], v.x, w5.x);  ffma2(acc[bb][4 + c2], v.y, w5.y); \
        }                                                                       \
    }

    for (int st = 0; st < TT; ++st) {
        const int t   = dir ? (TT - 1 - st) : st;
        const int par = st & 1;

        // ---- stage x(t) rows [b0, b0+8) -> xbuf ----
        {
            const float* xrowbase = p.x + ((size_t)t * BB + b0) * HH;
            #pragma unroll
            for (int r = 0; r < 16; ++r) {
                int idx = tidg + r * 64;           // 1024 float4s for the group
                int row = idx >> 7;                // 0..7
                int kk  = (idx & 127) << 2;
                float4 v = __ldg((const float4*)(xrowbase + (size_t)row * HH + kk));
                *(float4*)&xbuf[(b0 + row) * STR + kk] = v;
            }
        }
        GBAR(g);

        // accumulators: [bb][jj*4 + ch], ch: 0=r, 1=c, 2=n_x, 3=n_h
        unsigned long long acc[8][8];
        #pragma unroll
        for (int bb = 0; bb < 8; ++bb)
            #pragma unroll
            for (int q = 0; q < 8; ++q) acc[bb][q] = 0ull;

        // ---- x-GEMM (hides own-network barrier latency) ----
        #pragma unroll
        for (int i = 0; i < 8; ++i) GEMM_ITER(WxB, xbuf, 0, 1, 2)

        // ---- wait for h(t) on this group's network ----
        if (leader) {
            while (ld_acquire(&g_gen[dir][g]) - base < (unsigned)(st + 1)) { }
        }
        GBAR(g);

        // ---- stage h(t) rows [b0, b0+8) -> hbuf (L2-coherent loads) ----
        {
            const float* hrowbase = (const float*)g_h[dir][par] + (size_t)b0 * HH;
            #pragma unroll
            for (int r = 0; r < 16; ++r) {
                int idx = tidg + r * 64;
                int row = idx >> 7;
                int kk  = (idx & 127) << 2;
                float4 v = __ldcv((const float4*)(hrowbase + (size_t)row * HH + kk));
                *(float4*)&hbuf[(b0 + row) * STR + kk] = v;
            }
        }
        GBAR(g);

        // ---- h-GEMM ----
        #pragma unroll
        for (int i = 0; i < 8; ++i) GEMM_ITER(WhB, hbuf, 0, 1, 3)

        // ---- collapse f32x2 pairs ----
        float a64[8][8];
        #pragma unroll
        for (int bb = 0; bb < 8; ++bb)
            #pragma unroll
            for (int q = 0; q < 8; ++q)
                a64[bb][q] = u64lo(acc[bb][q]) + u64hi(acc[bb][q]);

        // ---- targeted exchange reduction over the 16 k-split lanes ----
        const bool hi8 = (s & 8) != 0;
        float r32[8][4];
        #pragma unroll
        for (int bb = 0; bb < 8; ++bb)
            #pragma unroll
            for (int ch = 0; ch < 4; ++ch) {
                float mine = hi8 ? a64[bb][4 + ch] : a64[bb][ch];
                float oth  = hi8 ? a64[bb][ch]     : a64[bb][4 + ch];
                r32[bb][ch] = mine + __shfl_xor_sync(0xffffffffu, oth, 8);
            }
        const bool hi4 = (s & 4) != 0;
        float r16[4][4];
        #pragma unroll
        for (int bl = 0; bl < 4; ++bl)
            #pragma unroll
            for (int ch = 0; ch < 4; ++ch) {
                float mine = hi4 ? r32[bl + 4][ch] : r32[bl][ch];
                float oth  = hi4 ? r32[bl][ch]     : r32[bl + 4][ch];
                r16[bl][ch] = mine + __shfl_xor_sync(0xffffffffu, oth, 4);
            }
        const bool hi2 = (s & 2) != 0;
        float r8[2][4];
        #pragma unroll
        for (int bl = 0; bl < 2; ++bl)
            #pragma unroll
            for (int ch = 0; ch < 4; ++ch) {
                float mine = hi2 ? r16[bl + 2][ch] : r16[bl][ch];
                float oth  = hi2 ? r16[bl][ch]     : r16[bl + 2][ch];
                r8[bl][ch] = mine + __shfl_xor_sync(0xffffffffu, oth, 2);
            }
        const bool hi1 = (s & 1) != 0;
        float r4v[4];
        #pragma unroll
        for (int ch = 0; ch < 4; ++ch) {
            float mine = hi1 ? r8[1][ch] : r8[0][ch];
            float oth  = hi1 ? r8[0][ch] : r8[1][ch];
            r4v[ch] = mine + __shfl_xor_sync(0xffffffffu, oth, 1);
        }

        // ---- activations + state update ----
        const float rg = fast_sigmoid(r4v[0] + c_br);
        const float cg = fast_sigmoid(r4v[1] + c_bi);
        const float ng = fast_tanh(r4v[2] + c_bni + rg * (r4v[3] + c_bnh));
        const float hold = hbuf[myb * STR + jcol];
        const float hnew = ng + cg * (hold - ng);

        g_h[dir][par ^ 1][myb * HH + jcol] = hnew;
        out[((size_t)t * BB + myb) * (2 * HH) + dir * HH + jcol] = hnew;

        GBAR(g);                              // group stores complete
        if (leader) net_arrive(dir, g, grpIdx);
    }
#undef GEMM_ITER
}

// ----------------------------------------------------------------------------
// Launch. Input order: x, Wri_f,Wci_f,Wni_f,Wrh_f,Wch_f,Wnh_f,br_f,bi_f,bni_f,
// bnh_f, Wri_b,Wci_b,Wni_b,Wrh_b,Wch_b,Wnh_b,br_b,bi_b,bni_b,bnh_b
// ----------------------------------------------------------------------------
extern "C" void kernel_launch(void* const* d_in, const int* in_sizes, int n_in,
                              void* d_out, int out_size)
{
    (void)in_sizes; (void)n_in; (void)out_size;

    Args a;
    a.x = (const float*)d_in[0];
    a.Wxi[0][0] = (const float*)d_in[1];
    a.Wxi[0][1] = (const float*)d_in[2];
    a.Wxi[0][2] = (const float*)d_in[3];
    a.Whh[0][0] = (const float*)d_in[4];
    a.Whh[0][1] = (const float*)d_in[5];
    a.Whh[0][2] = (const float*)d_in[6];
    a.br [0] = (const float*)d_in[7];
    a.bi [0] = (const float*)d_in[8];
    a.bni[0] = (const float*)d_in[9];
    a.bnh[0] = (const float*)d_in[10];
    a.Wxi[1][0] = (const float*)d_in[11];
    a.Wxi[1][1] = (const float*)d_in[12];
    a.Wxi[1][2] = (const float*)d_in[13];
    a.Whh[1][0] = (const float*)d_in[14];
    a.Whh[1][1] = (const float*)d_in[15];
    a.Whh[1][2] = (const float*)d_in[16];
    a.br [1] = (const float*)d_in[17];
    a.bi [1] = (const float*)d_in[18];
    a.bni[1] = (const float*)d_in[19];
    a.bnh[1] = (const float*)d_in[20];
    a.out = (float*)d_out;

    const int smem = (48 * STR + 64 * STR) * (int)sizeof(float);   // ~226 KB
    cudaFuncSetAttribute(gru_fused, cudaFuncAttributeMaxDynamicSharedMemorySize, smem);
    gru_fused<<<2 * NB, 256, smem>>>(a);
}